// round 1
// baseline (speedup 1.0000x reference)
#include <cuda_runtime.h>
#include <math.h>

#define NN   50000
#define EE   1600000
#define CIN  32
#define HID  128
#define LAT  64
#define HID4 (HID/4)
#define CIN4 (CIN/4)

// ---------------- scratch (device globals; no allocations allowed) ----------
__device__ __align__(16) float g_deg[NN];
__device__ __align__(16) float g_dis[NN];
__device__ __align__(16) float g_aggx[NN * CIN];   // aggregated raw features (layer1 trick)
__device__ __align__(16) float g_bufA[NN * HID];   // h1, then agg2, then h2
__device__ __align__(16) float g_bufB[NN * HID];   // t2 = h1 @ W2
__device__ __align__(16) float g_gsum[HID];
__device__ __align__(16) float g_dvec[HID];

// vector reduction to global memory (sm_90+): one 16B atomic instead of 4 scalar
__device__ __forceinline__ void red_add_f4(float4* p, float4 v) {
    asm volatile("red.global.add.v4.f32 [%0], {%1,%2,%3,%4};"
                 :: "l"(p), "f"(v.x), "f"(v.y), "f"(v.z), "f"(v.w)
                 : "memory");
}

// ---------------- init: deg=1 (self loop), zero aggx + gsum -----------------
__global__ void k_init() {
    int i = blockIdx.x * 256 + threadIdx.x;
    if (i < NN * CIN4) ((float4*)g_aggx)[i] = make_float4(0.f, 0.f, 0.f, 0.f);
    if (i < NN)  g_deg[i]  = 1.0f;
    if (i < HID) g_gsum[i] = 0.0f;
}

// ---------------- degree over dst ------------------------------------------
__global__ void k_deg(const int* __restrict__ dst) {
    int e = blockIdx.x * 256 + threadIdx.x;
    if (e < EE) atomicAdd(&g_deg[dst[e]], 1.0f);
}

__global__ void k_dis() {
    int i = blockIdx.x * 256 + threadIdx.x;
    if (i < NN) g_dis[i] = rsqrtf(g_deg[i]);
}

// ---------------- layer-1 scatter on RAW x (32 cols): 8 lanes / edge -------
__global__ void __launch_bounds__(256) k_scatter32(const float* __restrict__ x,
                                                   const int* __restrict__ ei) {
    int t = blockIdx.x * 256 + threadIdx.x;
    int e = t >> 3;            // edge
    int l = t & 7;             // float4 lane within the 32-col row
    if (e >= EE) return;
    int s = ei[e];
    int d = ei[EE + e];
    float nrm = g_dis[s] * g_dis[d];
    float4 v = ((const float4*)x)[s * CIN4 + l];
    v.x *= nrm; v.y *= nrm; v.z *= nrm; v.w *= nrm;
    red_add_f4(((float4*)g_aggx) + d * CIN4 + l, v);
}

// ---------------- layer 1: h1 = relu((aggx + x*dis^2) @ W1 + b1) -> bufA ---
__global__ void __launch_bounds__(256) k_layer1(const float* __restrict__ x,
                                                const float* __restrict__ W1,
                                                const float* __restrict__ b1) {
    __shared__ float sW[CIN * HID];   // 16 KB
    __shared__ float sv[8 * CIN];     // 8 rows of pre-aggregated input
    int tid = threadIdx.x;
    int row0 = blockIdx.x * 8;
    for (int i = tid; i < CIN * HID; i += 256) sW[i] = W1[i];
    {
        int r = tid >> 5, c = tid & 31;       // tid == r*32 + c
        int i = row0 + r;
        float sc = g_dis[i]; sc *= sc;
        sv[tid] = fmaf(x[i * CIN + c], sc, g_aggx[i * CIN + c]);
    }
    __syncthreads();
    int r = tid >> 5, cg = tid & 31;
    float4 acc = ((const float4*)b1)[cg];
    const float4* sW4 = (const float4*)sW;
#pragma unroll
    for (int k = 0; k < CIN; k++) {
        float a = sv[r * CIN + k];
        float4 w = sW4[k * HID4 + cg];
        acc.x = fmaf(a, w.x, acc.x); acc.y = fmaf(a, w.y, acc.y);
        acc.z = fmaf(a, w.z, acc.z); acc.w = fmaf(a, w.w, acc.w);
    }
    acc.x = fmaxf(acc.x, 0.f); acc.y = fmaxf(acc.y, 0.f);
    acc.z = fmaxf(acc.z, 0.f); acc.w = fmaxf(acc.w, 0.f);
    ((float4*)g_bufA)[(row0 + r) * HID4 + cg] = acc;
}

// ---------------- GEMM2: bufB = bufA @ W2  (no bias here) ------------------
// 256 thr = 32 col-groups x 8 row-lanes; each thread does 4 rows x 4 cols.
__global__ void __launch_bounds__(256) k_gemm2(const float* __restrict__ W2) {
    int tid = threadIdx.x;
    int cg = tid & 31, rl = tid >> 5;
    int rbase = blockIdx.x * 32 + rl;
    int r0 = rbase, r1 = rbase + 8, r2 = rbase + 16, r3 = rbase + 24;
    bool v0 = r0 < NN, v1 = r1 < NN, v2 = r2 < NN, v3 = r3 < NN;
    const float4* W4 = (const float4*)W2;
    const float* A = g_bufA;
    float4 a0 = make_float4(0.f,0.f,0.f,0.f), a1 = a0, a2 = a0, a3 = a0;
#pragma unroll 4
    for (int k = 0; k < HID; k++) {
        float4 w = __ldg(&W4[k * HID4 + cg]);
        float x0 = v0 ? __ldg(&A[r0 * HID + k]) : 0.f;
        float x1 = v1 ? __ldg(&A[r1 * HID + k]) : 0.f;
        float x2 = v2 ? __ldg(&A[r2 * HID + k]) : 0.f;
        float x3 = v3 ? __ldg(&A[r3 * HID + k]) : 0.f;
        a0.x = fmaf(x0,w.x,a0.x); a0.y = fmaf(x0,w.y,a0.y); a0.z = fmaf(x0,w.z,a0.z); a0.w = fmaf(x0,w.w,a0.w);
        a1.x = fmaf(x1,w.x,a1.x); a1.y = fmaf(x1,w.y,a1.y); a1.z = fmaf(x1,w.z,a1.z); a1.w = fmaf(x1,w.w,a1.w);
        a2.x = fmaf(x2,w.x,a2.x); a2.y = fmaf(x2,w.y,a2.y); a2.z = fmaf(x2,w.z,a2.z); a2.w = fmaf(x2,w.w,a2.w);
        a3.x = fmaf(x3,w.x,a3.x); a3.y = fmaf(x3,w.y,a3.y); a3.z = fmaf(x3,w.z,a3.z); a3.w = fmaf(x3,w.w,a3.w);
    }
    float4* O = (float4*)g_bufB;
    if (v0) O[r0 * HID4 + cg] = a0;
    if (v1) O[r1 * HID4 + cg] = a1;
    if (v2) O[r2 * HID4 + cg] = a2;
    if (v3) O[r3 * HID4 + cg] = a3;
}

// ---------------- zero bufA (becomes agg2 target) --------------------------
__global__ void k_zeroA() {
    int i = blockIdx.x * 256 + threadIdx.x;
    if (i < NN * HID4) ((float4*)g_bufA)[i] = make_float4(0.f, 0.f, 0.f, 0.f);
}

// ---------------- layer-2 scatter on t2 (128 cols): warp / edge ------------
__global__ void __launch_bounds__(256) k_scatter128(const int* __restrict__ ei) {
    int gw = (blockIdx.x * 256 + threadIdx.x) >> 5;   // edge (grid exact: EE warps)
    int lane = threadIdx.x & 31;
    int s = 0, d = 0; float nrm = 0.f;
    if (lane == 0) {
        s = ei[gw]; d = ei[EE + gw];
        nrm = g_dis[s] * g_dis[d];
    }
    s = __shfl_sync(0xffffffffu, s, 0);
    d = __shfl_sync(0xffffffffu, d, 0);
    nrm = __shfl_sync(0xffffffffu, nrm, 0);
    float4 v = ((const float4*)g_bufB)[s * HID4 + lane];
    v.x *= nrm; v.y *= nrm; v.z *= nrm; v.w *= nrm;
    red_add_f4(((float4*)g_bufA) + d * HID4 + lane, v);
}

// ---------------- fuse2: bufA = relu(bufA + bufB*dis^2 + b2) = h2 ----------
__global__ void k_fuse2(const float* __restrict__ b2) {
    int idx = blockIdx.x * 256 + threadIdx.x;
    if (idx >= NN * HID4) return;
    int i = idx >> 5;
    float sc = g_dis[i]; sc *= sc;
    float4 a = ((float4*)g_bufA)[idx];
    float4 t = ((const float4*)g_bufB)[idx];
    float4 b = ((const float4*)b2)[idx & 31];
    a.x = fmaxf(fmaf(t.x, sc, a.x) + b.x, 0.f);
    a.y = fmaxf(fmaf(t.y, sc, a.y) + b.y, 0.f);
    a.z = fmaxf(fmaf(t.z, sc, a.z) + b.z, 0.f);
    a.w = fmaxf(fmaf(t.w, sc, a.w) + b.w, 0.f);
    ((float4*)g_bufA)[idx] = a;
}

// ---------------- mean pool over rows of bufA -> g_gsum (sum) --------------
__global__ void __launch_bounds__(256) k_mean() {
    __shared__ float sred[256];
    int tid = threadIdx.x;
    int c = tid & 127, half = tid >> 7;
    float acc = 0.f;
    for (int i = blockIdx.x * 2 + half; i < NN; i += gridDim.x * 2)
        acc += g_bufA[i * HID + c];
    sred[tid] = acc;
    __syncthreads();
    if (tid < 128) atomicAdd(&g_gsum[c], sred[tid] + sred[tid + 128]);
}

// ---------------- head: mu, logvar (to out), z, d -> g_dvec ----------------
__global__ void __launch_bounds__(128) k_head(const float* __restrict__ eps,
                                              const float* __restrict__ Wmu, const float* __restrict__ bmu,
                                              const float* __restrict__ Wlv, const float* __restrict__ blv,
                                              const float* __restrict__ Wd1, const float* __restrict__ bd1,
                                              float* __restrict__ out) {
    __shared__ float gs[HID], zs[LAT];
    int tid = threadIdx.x;
    gs[tid] = g_gsum[tid] * (1.0f / (float)NN);
    __syncthreads();
    if (tid < LAT) {
        float mu = bmu[tid], lv = blv[tid];
#pragma unroll 4
        for (int k = 0; k < HID; k++) {
            float gk = gs[k];
            mu = fmaf(gk, Wmu[k * LAT + tid], mu);
            lv = fmaf(gk, Wlv[k * LAT + tid], lv);
        }
        out[(size_t)NN * CIN + tid] = mu;
        out[(size_t)NN * CIN + LAT + tid] = lv;
        zs[tid] = fmaf(eps[tid], expf(0.5f * lv), mu);
    }
    __syncthreads();
    float dv = bd1[tid];
#pragma unroll 4
    for (int k = 0; k < LAT; k++) dv = fmaf(zs[k], Wd1[k * HID + tid], dv);
    g_dvec[tid] = fmaxf(dv, 0.f);
}

// ---------------- decoder GEMV: out = d @ Wd2 + bd2 (819 MB stream) --------
__global__ void __launch_bounds__(256) k_dec(const float* __restrict__ Wd2,
                                             const float* __restrict__ bd2,
                                             float* __restrict__ out) {
    __shared__ float ds[HID];
    int tid = threadIdx.x;
    if (tid < HID) ds[tid] = g_dvec[tid];
    __syncthreads();
    int j = blockIdx.x * 256 + tid;              // float4 column index
    const int NC4 = NN * CIN / 4;                // 400000
    if (j >= NC4) return;
    const float4* W = (const float4*)Wd2;
    float4 acc = ((const float4*)bd2)[j];
#pragma unroll 8
    for (int k = 0; k < HID; k++) {
        float dk = ds[k];
        float4 w = W[(size_t)k * NC4 + j];
        acc.x = fmaf(dk, w.x, acc.x); acc.y = fmaf(dk, w.y, acc.y);
        acc.z = fmaf(dk, w.z, acc.z); acc.w = fmaf(dk, w.w, acc.w);
    }
    ((float4*)out)[j] = acc;
}

// ---------------- launch ----------------------------------------------------
extern "C" void kernel_launch(void* const* d_in, const int* in_sizes, int n_in,
                              void* d_out, int out_size) {
    const float* x   = (const float*)d_in[0];
    const int*   ei  = (const int*)  d_in[1];
    const float* eps = (const float*)d_in[2];
    const float* W1  = (const float*)d_in[3];
    const float* b1  = (const float*)d_in[4];
    const float* W2  = (const float*)d_in[5];
    const float* b2  = (const float*)d_in[6];
    const float* Wmu = (const float*)d_in[7];
    const float* bmu = (const float*)d_in[8];
    const float* Wlv = (const float*)d_in[9];
    const float* blv = (const float*)d_in[10];
    const float* Wd1 = (const float*)d_in[11];
    const float* bd1 = (const float*)d_in[12];
    const float* Wd2 = (const float*)d_in[13];
    const float* bd2 = (const float*)d_in[14];
    float* out = (float*)d_out;

    (void)in_sizes; (void)n_in; (void)out_size;

    k_init     <<<(NN * CIN4 + 255) / 256, 256>>>();
    k_deg      <<<(EE + 255) / 256, 256>>>(ei + EE);
    k_dis      <<<(NN + 255) / 256, 256>>>();
    k_scatter32<<<EE * 8 / 256, 256>>>(x, ei);          // 50000 blocks
    k_layer1   <<<NN / 8, 256>>>(x, W1, b1);            // 6250 blocks
    k_gemm2    <<<(NN + 31) / 32, 256>>>(W2);           // 1563 blocks
    k_zeroA    <<<(NN * HID4 + 255) / 256, 256>>>();
    k_scatter128<<<EE * 32 / 256, 256>>>(ei);           // 200000 blocks
    k_fuse2    <<<(NN * HID4 + 255) / 256, 256>>>(b2);
    k_mean     <<<256, 256>>>();
    k_head     <<<1, 128>>>(eps, Wmu, bmu, Wlv, blv, Wd1, bd1, out);
    k_dec      <<<(NN * CIN / 4 + 255) / 256, 256>>>(Wd2, bd2, out);
}

// round 3
// speedup vs baseline: 1.1076x; 1.1076x over previous
#include <cuda_runtime.h>
#include <math.h>

#define NN   50000
#define EE   1600000
#define CIN  32
#define HID  128
#define LAT  64
#define HID4 (HID/4)
#define CIN4 (CIN/4)

// ---------------- scratch (device globals; no allocations allowed) ----------
__device__ int   g_ideg[NN];            // in-degree (edges only, no self loop)
__device__ int   g_cnt[NN];             // bucket-fill cursors
__device__ int   g_rowptr[NN + 1];      // CSR row pointers
__device__ int   g_col[EE];             // CSR column (src) indices
__device__ __align__(16) float g_dis[NN];
__device__ __align__(16) float g_aggx[NN * CIN];   // fused layer-1 GCN input
__device__ __align__(16) float g_bufA[NN * HID];   // h1, then h2
__device__ __align__(16) float g_bufB[NN * HID];   // t2 = h1 @ W2
__device__ __align__(16) float g_gsum[HID];
__device__ __align__(16) float g_dvec[HID];

// ---------------- init: zero counters -------------------------------------
__global__ void k_init() {
    int i = blockIdx.x * 256 + threadIdx.x;
    if (i < NN)  { g_ideg[i] = 0; g_cnt[i] = 0; }
    if (i < HID) g_gsum[i] = 0.0f;
}

// ---------------- integer degree over dst ----------------------------------
__global__ void k_deg(const int* __restrict__ dst) {
    int e = blockIdx.x * 256 + threadIdx.x;
    if (e < EE) atomicAdd(&g_ideg[dst[e]], 1);
}

// ---------------- single-block exclusive scan -> rowptr; also dis -----------
__global__ void __launch_bounds__(1024) k_scan() {
    __shared__ int sdata[1024];
    __shared__ int sbase;
    int tid = threadIdx.x;
    if (tid == 0) sbase = 0;
    __syncthreads();
    for (int t0 = 0; t0 < NN; t0 += 1024) {
        int i = t0 + tid;
        int d = (i < NN) ? g_ideg[i] : 0;
        sdata[tid] = d;
        __syncthreads();
        // Hillis-Steele inclusive scan over 1024
        for (int off = 1; off < 1024; off <<= 1) {
            int v = (tid >= off) ? sdata[tid - off] : 0;
            __syncthreads();
            sdata[tid] += v;
            __syncthreads();
        }
        if (i < NN) {
            g_rowptr[i] = sbase + sdata[tid] - d;      // exclusive
            g_dis[i] = rsqrtf((float)(d + 1));         // +1 self loop
        }
        __syncthreads();
        if (tid == 1023) sbase += sdata[1023];
        __syncthreads();
    }
    if (tid == 0) g_rowptr[NN] = sbase;
}

// ---------------- CSR bucket fill -------------------------------------------
__global__ void k_fill(const int* __restrict__ ei) {
    int e = blockIdx.x * 256 + threadIdx.x;
    if (e >= EE) return;
    int s = ei[e];
    int d = ei[EE + e];
    int pos = atomicAdd(&g_cnt[d], 1);
    g_col[g_rowptr[d] + pos] = s;
}

// ---------------- layer-1 gather: aggx = sum_nbr x[s]*nrm + x[i]*dis^2 ------
// one warp per node, lane = column (32 cols)
__global__ void __launch_bounds__(256) k_gather1(const float* __restrict__ x) {
    int w = (blockIdx.x * 256 + threadIdx.x) >> 5;
    int lane = threadIdx.x & 31;
    if (w >= NN) return;
    float di = g_dis[w];
    int e   = g_rowptr[w];
    int end = g_rowptr[w + 1];
    float acc = x[w * CIN + lane] * di * di;
    for (; e < end; e++) {
        int s = __ldg(&g_col[e]);
        float nrm = __ldg(&g_dis[s]) * di;
        acc = fmaf(__ldg(&x[s * CIN + lane]), nrm, acc);
    }
    g_aggx[w * CIN + lane] = acc;
}

// ---------------- layer 1: h1 = relu(aggx @ W1 + b1) -> bufA ----------------
__global__ void __launch_bounds__(256) k_layer1(const float* __restrict__ W1,
                                                const float* __restrict__ b1) {
    __shared__ float sW[CIN * HID];   // 16 KB
    __shared__ float sv[8 * CIN];     // 8 rows of input
    int tid = threadIdx.x;
    int row0 = blockIdx.x * 8;
    for (int i = tid; i < CIN * HID; i += 256) sW[i] = W1[i];
    sv[tid] = g_aggx[row0 * CIN + tid];
    __syncthreads();
    int r = tid >> 5, cg = tid & 31;
    float4 acc = ((const float4*)b1)[cg];
    const float4* sW4 = (const float4*)sW;
#pragma unroll
    for (int k = 0; k < CIN; k++) {
        float a = sv[r * CIN + k];
        float4 w = sW4[k * HID4 + cg];
        acc.x = fmaf(a, w.x, acc.x); acc.y = fmaf(a, w.y, acc.y);
        acc.z = fmaf(a, w.z, acc.z); acc.w = fmaf(a, w.w, acc.w);
    }
    acc.x = fmaxf(acc.x, 0.f); acc.y = fmaxf(acc.y, 0.f);
    acc.z = fmaxf(acc.z, 0.f); acc.w = fmaxf(acc.w, 0.f);
    ((float4*)g_bufA)[(row0 + r) * HID4 + cg] = acc;
}

// ---------------- GEMM2: bufB = bufA @ W2  (no bias) ------------------------
__global__ void __launch_bounds__(256) k_gemm2(const float* __restrict__ W2) {
    int tid = threadIdx.x;
    int cg = tid & 31, rl = tid >> 5;
    int rbase = blockIdx.x * 32 + rl;
    int r0 = rbase, r1 = rbase + 8, r2 = rbase + 16, r3 = rbase + 24;
    bool v0 = r0 < NN, v1 = r1 < NN, v2 = r2 < NN, v3 = r3 < NN;
    const float4* W4 = (const float4*)W2;
    const float* A = g_bufA;
    float4 a0 = make_float4(0.f,0.f,0.f,0.f), a1 = a0, a2 = a0, a3 = a0;
#pragma unroll 4
    for (int k = 0; k < HID; k++) {
        float4 w = __ldg(&W4[k * HID4 + cg]);
        float x0 = v0 ? __ldg(&A[r0 * HID + k]) : 0.f;
        float x1 = v1 ? __ldg(&A[r1 * HID + k]) : 0.f;
        float x2 = v2 ? __ldg(&A[r2 * HID + k]) : 0.f;
        float x3 = v3 ? __ldg(&A[r3 * HID + k]) : 0.f;
        a0.x = fmaf(x0,w.x,a0.x); a0.y = fmaf(x0,w.y,a0.y); a0.z = fmaf(x0,w.z,a0.z); a0.w = fmaf(x0,w.w,a0.w);
        a1.x = fmaf(x1,w.x,a1.x); a1.y = fmaf(x1,w.y,a1.y); a1.z = fmaf(x1,w.z,a1.z); a1.w = fmaf(x1,w.w,a1.w);
        a2.x = fmaf(x2,w.x,a2.x); a2.y = fmaf(x2,w.y,a2.y); a2.z = fmaf(x2,w.z,a2.z); a2.w = fmaf(x2,w.w,a2.w);
        a3.x = fmaf(x3,w.x,a3.x); a3.y = fmaf(x3,w.y,a3.y); a3.z = fmaf(x3,w.z,a3.z); a3.w = fmaf(x3,w.w,a3.w);
    }
    float4* O = (float4*)g_bufB;
    if (v0) O[r0 * HID4 + cg] = a0;
    if (v1) O[r1 * HID4 + cg] = a1;
    if (v2) O[r2 * HID4 + cg] = a2;
    if (v3) O[r3 * HID4 + cg] = a3;
}

// ---------------- layer-2 gather + self + bias + relu -> bufA (= h2) --------
// one warp per node, lane = float4 column group (128 cols)
__global__ void __launch_bounds__(256) k_gather2(const float* __restrict__ b2) {
    int w = (blockIdx.x * 256 + threadIdx.x) >> 5;
    int lane = threadIdx.x & 31;
    if (w >= NN) return;
    float di = g_dis[w];
    int e   = g_rowptr[w];
    int end = g_rowptr[w + 1];
    const float4* T = (const float4*)g_bufB;
    float sc = di * di;
    float4 self = T[w * HID4 + lane];
    float4 acc;
    acc.x = self.x * sc; acc.y = self.y * sc;
    acc.z = self.z * sc; acc.w = self.w * sc;
    for (; e < end; e++) {
        int s = __ldg(&g_col[e]);
        float nrm = __ldg(&g_dis[s]) * di;
        float4 v = __ldg(&T[s * HID4 + lane]);
        acc.x = fmaf(v.x, nrm, acc.x); acc.y = fmaf(v.y, nrm, acc.y);
        acc.z = fmaf(v.z, nrm, acc.z); acc.w = fmaf(v.w, nrm, acc.w);
    }
    float4 b = ((const float4*)b2)[lane];
    acc.x = fmaxf(acc.x + b.x, 0.f); acc.y = fmaxf(acc.y + b.y, 0.f);
    acc.z = fmaxf(acc.z + b.z, 0.f); acc.w = fmaxf(acc.w + b.w, 0.f);
    ((float4*)g_bufA)[w * HID4 + lane] = acc;
}

// ---------------- mean pool over rows of bufA -> g_gsum (sum) ---------------
__global__ void __launch_bounds__(256) k_mean() {
    __shared__ float sred[256];
    int tid = threadIdx.x;
    int c = tid & 127, half = tid >> 7;
    float acc = 0.f;
    for (int i = blockIdx.x * 2 + half; i < NN; i += gridDim.x * 2)
        acc += g_bufA[i * HID + c];
    sred[tid] = acc;
    __syncthreads();
    if (tid < 128) atomicAdd(&g_gsum[c], sred[tid] + sred[tid + 128]);
}

// ---------------- head: mu, logvar (to out), z, d -> g_dvec -----------------
__global__ void __launch_bounds__(128) k_head(const float* __restrict__ eps,
                                              const float* __restrict__ Wmu, const float* __restrict__ bmu,
                                              const float* __restrict__ Wlv, const float* __restrict__ blv,
                                              const float* __restrict__ Wd1, const float* __restrict__ bd1,
                                              float* __restrict__ out) {
    __shared__ float gs[HID], zs[LAT];
    int tid = threadIdx.x;
    gs[tid] = g_gsum[tid] * (1.0f / (float)NN);
    __syncthreads();
    if (tid < LAT) {
        float mu = bmu[tid], lv = blv[tid];
#pragma unroll 4
        for (int k = 0; k < HID; k++) {
            float gk = gs[k];
            mu = fmaf(gk, Wmu[k * LAT + tid], mu);
            lv = fmaf(gk, Wlv[k * LAT + tid], lv);
        }
        out[(size_t)NN * CIN + tid] = mu;
        out[(size_t)NN * CIN + LAT + tid] = lv;
        zs[tid] = fmaf(eps[tid], expf(0.5f * lv), mu);
    }
    __syncthreads();
    float dv = bd1[tid];
#pragma unroll 4
    for (int k = 0; k < LAT; k++) dv = fmaf(zs[k], Wd1[k * HID + tid], dv);
    g_dvec[tid] = fmaxf(dv, 0.f);
}

// ---------------- decoder GEMV: out = d @ Wd2 + bd2 (819 MB stream) ---------
__global__ void __launch_bounds__(256) k_dec(const float* __restrict__ Wd2,
                                             const float* __restrict__ bd2,
                                             float* __restrict__ out) {
    __shared__ float ds[HID];
    int tid = threadIdx.x;
    if (tid < HID) ds[tid] = g_dvec[tid];
    __syncthreads();
    int j = blockIdx.x * 256 + tid;              // float4 column index
    const int NC4 = NN * CIN / 4;                // 400000
    if (j >= NC4) return;
    const float4* W = (const float4*)Wd2;
    float4 acc = ((const float4*)bd2)[j];
#pragma unroll 8
    for (int k = 0; k < HID; k++) {
        float dk = ds[k];
        float4 w = W[(size_t)k * NC4 + j];
        acc.x = fmaf(dk, w.x, acc.x); acc.y = fmaf(dk, w.y, acc.y);
        acc.z = fmaf(dk, w.z, acc.z); acc.w = fmaf(dk, w.w, acc.w);
    }
    ((float4*)out)[j] = acc;
}

// ---------------- launch ----------------------------------------------------
extern "C" void kernel_launch(void* const* d_in, const int* in_sizes, int n_in,
                              void* d_out, int out_size) {
    const float* x   = (const float*)d_in[0];
    const int*   ei  = (const int*)  d_in[1];
    const float* eps = (const float*)d_in[2];
    const float* W1  = (const float*)d_in[3];
    const float* b1  = (const float*)d_in[4];
    const float* W2  = (const float*)d_in[5];
    const float* b2  = (const float*)d_in[6];
    const float* Wmu = (const float*)d_in[7];
    const float* bmu = (const float*)d_in[8];
    const float* Wlv = (const float*)d_in[9];
    const float* blv = (const float*)d_in[10];
    const float* Wd1 = (const float*)d_in[11];
    const float* bd1 = (const float*)d_in[12];
    const float* Wd2 = (const float*)d_in[13];
    const float* bd2 = (const float*)d_in[14];
    float* out = (float*)d_out;

    (void)in_sizes; (void)n_in; (void)out_size;

    k_init   <<<(NN + 255) / 256, 256>>>();
    k_deg    <<<(EE + 255) / 256, 256>>>(ei + EE);
    k_scan   <<<1, 1024>>>();
    k_fill   <<<(EE + 255) / 256, 256>>>(ei);
    k_gather1<<<NN * 32 / 256, 256>>>(x);            // 6250 blocks, warp/node
    k_layer1 <<<NN / 8, 256>>>(W1, b1);              // 6250 blocks
    k_gemm2  <<<(NN + 31) / 32, 256>>>(W2);          // 1563 blocks
    k_gather2<<<NN * 32 / 256, 256>>>(b2);           // 6250 blocks, warp/node
    k_mean   <<<256, 256>>>();
    k_head   <<<1, 128>>>(eps, Wmu, bmu, Wlv, blv, Wd1, bd1, out);
    k_dec    <<<(NN * CIN / 4 + 255) / 256, 256>>>(Wd2, bd2, out);
}

// round 6
// speedup vs baseline: 1.1157x; 1.0073x over previous
#include <cuda_runtime.h>
#include <math.h>

#define NN   50000
#define EE   1600000
#define CIN  32
#define HID  128
#define LAT  64
#define HID4 (HID/4)
#define CIN4 (CIN/4)

// ---------------- scratch (device globals; no allocations allowed) ----------
__device__ int   g_ideg[NN];            // in-degree (edges only, no self loop)
__device__ int   g_cnt[NN];             // bucket-fill cursors
__device__ int   g_rowptr[NN + 1];      // CSR row pointers
__device__ int   g_col[EE];             // CSR column (src) indices
__device__ __align__(16) float g_dis[NN];
__device__ __align__(16) float g_aggx[NN * CIN];   // fused layer-1 GCN input
__device__ __align__(16) float g_bufA[NN * HID];   // h1, then h2
__device__ __align__(16) float g_bufB[NN * HID];   // t2 = h1 @ W2
__device__ __align__(16) float g_gsum[HID];
__device__ __align__(16) float g_dvec[HID];

__device__ __forceinline__ void fma4(float4& acc, float s, const float4& v) {
    acc.x = fmaf(s, v.x, acc.x);
    acc.y = fmaf(s, v.y, acc.y);
    acc.z = fmaf(s, v.z, acc.z);
    acc.w = fmaf(s, v.w, acc.w);
}

// ---------------- init: zero counters -------------------------------------
__global__ void k_init() {
    int i = blockIdx.x * 256 + threadIdx.x;
    if (i < NN)  { g_ideg[i] = 0; g_cnt[i] = 0; }
    if (i < HID) g_gsum[i] = 0.0f;
}

// ---------------- integer degree over dst: 4 edges / thread ----------------
__global__ void k_deg(const int* __restrict__ dst) {
    int e0 = (blockIdx.x * 256 + threadIdx.x) * 4;
    if (e0 >= EE) return;                      // EE % 4 == 0 -> full quad
    int4 d4 = *(const int4*)(dst + e0);
    atomicAdd(&g_ideg[d4.x], 1);
    atomicAdd(&g_ideg[d4.y], 1);
    atomicAdd(&g_ideg[d4.z], 1);
    atomicAdd(&g_ideg[d4.w], 1);
}

// ---------------- single-block scan: serial chunks + warp shuffles ----------
__global__ void __launch_bounds__(1024) k_scan() {
    const int CH = 49;                         // ceil(50000/1024)
    int tid = threadIdx.x;
    int base = tid * CH;
    int local = 0;
#pragma unroll
    for (int j = 0; j < CH; j++) {
        int i = base + j;
        if (i < NN) local += g_ideg[i];
    }
    __shared__ int wsum[32];
    int lane = tid & 31, wid = tid >> 5;
    int inc = local;
#pragma unroll
    for (int off = 1; off < 32; off <<= 1) {
        int t = __shfl_up_sync(0xffffffffu, inc, off);
        if (lane >= off) inc += t;
    }
    if (lane == 31) wsum[wid] = inc;
    __syncthreads();
    if (wid == 0) {
        int v = wsum[lane];
#pragma unroll
        for (int off = 1; off < 32; off <<= 1) {
            int t = __shfl_up_sync(0xffffffffu, v, off);
            if (lane >= off) v += t;
        }
        wsum[lane] = v;
    }
    __syncthreads();
    int run = inc - local + (wid > 0 ? wsum[wid - 1] : 0);   // exclusive prefix
#pragma unroll
    for (int j = 0; j < CH; j++) {
        int i = base + j;
        if (i < NN) {
            int d = g_ideg[i];
            g_rowptr[i] = run;
            g_dis[i] = rsqrtf((float)(d + 1));               // +1 self loop
            run += d;
        }
    }
    if (tid == 1023) g_rowptr[NN] = run;
}

// ---------------- CSR bucket fill: 4 edges / thread -------------------------
__global__ void k_fill(const int* __restrict__ ei) {
    int e0 = (blockIdx.x * 256 + threadIdx.x) * 4;
    if (e0 >= EE) return;
    int4 s4 = *(const int4*)(ei + e0);
    int4 d4 = *(const int4*)(ei + EE + e0);
    int p0 = atomicAdd(&g_cnt[d4.x], 1);
    int p1 = atomicAdd(&g_cnt[d4.y], 1);
    int p2 = atomicAdd(&g_cnt[d4.z], 1);
    int p3 = atomicAdd(&g_cnt[d4.w], 1);
    int r0 = __ldg(&g_rowptr[d4.x]);
    int r1 = __ldg(&g_rowptr[d4.y]);
    int r2 = __ldg(&g_rowptr[d4.z]);
    int r3 = __ldg(&g_rowptr[d4.w]);
    g_col[r0 + p0] = s4.x;
    g_col[r1 + p1] = s4.y;
    g_col[r2 + p2] = s4.z;
    g_col[r3 + p3] = s4.w;
}

// ---------------- layer-1 gather (32 cols), warp/node, 4x unroll ------------
__global__ void __launch_bounds__(256) k_gather1(const float* __restrict__ x) {
    int w = (blockIdx.x * 256 + threadIdx.x) >> 5;
    int lane = threadIdx.x & 31;
    if (w >= NN) return;
    float di = g_dis[w];
    int e   = g_rowptr[w];
    int end = g_rowptr[w + 1];
    float acc = x[w * CIN + lane] * di * di;
    int e4 = e + ((end - e) & ~3);
    for (; e < e4; e += 4) {
        int s0 = __ldg(&g_col[e]);
        int s1 = __ldg(&g_col[e + 1]);
        int s2 = __ldg(&g_col[e + 2]);
        int s3 = __ldg(&g_col[e + 3]);
        float n0 = __ldg(&g_dis[s0]) * di;
        float n1 = __ldg(&g_dis[s1]) * di;
        float n2 = __ldg(&g_dis[s2]) * di;
        float n3 = __ldg(&g_dis[s3]) * di;
        float v0 = __ldg(&x[s0 * CIN + lane]);
        float v1 = __ldg(&x[s1 * CIN + lane]);
        float v2 = __ldg(&x[s2 * CIN + lane]);
        float v3 = __ldg(&x[s3 * CIN + lane]);
        acc = fmaf(v0, n0, acc);
        acc = fmaf(v1, n1, acc);
        acc = fmaf(v2, n2, acc);
        acc = fmaf(v3, n3, acc);
    }
    for (; e < end; e++) {
        int s = __ldg(&g_col[e]);
        acc = fmaf(__ldg(&x[s * CIN + lane]), __ldg(&g_dis[s]) * di, acc);
    }
    g_aggx[w * CIN + lane] = acc;
}

// ---------------- layer 1: h1 = relu(aggx @ W1 + b1) -> bufA ----------------
__global__ void __launch_bounds__(256) k_layer1(const float* __restrict__ W1,
                                                const float* __restrict__ b1) {
    __shared__ float sW[CIN * HID];   // 16 KB
    __shared__ float sv[8 * CIN];     // 8 rows of input
    int tid = threadIdx.x;
    int row0 = blockIdx.x * 8;
    for (int i = tid; i < CIN * HID; i += 256) sW[i] = W1[i];
    sv[tid] = g_aggx[row0 * CIN + tid];
    __syncthreads();
    int r = tid >> 5, cg = tid & 31;
    float4 acc = ((const float4*)b1)[cg];
    const float4* sW4 = (const float4*)sW;
#pragma unroll
    for (int k = 0; k < CIN; k++) {
        float a = sv[r * CIN + k];
        fma4(acc, a, sW4[k * HID4 + cg]);
    }
    acc.x = fmaxf(acc.x, 0.f); acc.y = fmaxf(acc.y, 0.f);
    acc.z = fmaxf(acc.z, 0.f); acc.w = fmaxf(acc.w, 0.f);
    ((float4*)g_bufA)[(row0 + r) * HID4 + cg] = acc;
}

// ---------------- GEMM2: bufB = bufA @ W2, float4 A broadcast loads ---------
__global__ void __launch_bounds__(256) k_gemm2(const float* __restrict__ W2) {
    int tid = threadIdx.x;
    int cg = tid & 31, rl = tid >> 5;
    int rbase = blockIdx.x * 32 + rl;
    int r0 = rbase, r1 = rbase + 8, r2 = rbase + 16, r3 = rbase + 24;
    bool v0 = r0 < NN, v1 = r1 < NN, v2 = r2 < NN, v3 = r3 < NN;
    const float4* W4 = (const float4*)W2;
    const float4* A4 = (const float4*)g_bufA;
    float4 zf = make_float4(0.f, 0.f, 0.f, 0.f);
    float4 a0 = zf, a1 = zf, a2 = zf, a3 = zf;
#pragma unroll 4
    for (int k4 = 0; k4 < HID4; k4++) {
        float4 x0 = v0 ? __ldg(&A4[r0 * HID4 + k4]) : zf;
        float4 x1 = v1 ? __ldg(&A4[r1 * HID4 + k4]) : zf;
        float4 x2 = v2 ? __ldg(&A4[r2 * HID4 + k4]) : zf;
        float4 x3 = v3 ? __ldg(&A4[r3 * HID4 + k4]) : zf;
        float4 w0 = __ldg(&W4[(k4 * 4 + 0) * HID4 + cg]);
        float4 w1 = __ldg(&W4[(k4 * 4 + 1) * HID4 + cg]);
        float4 w2 = __ldg(&W4[(k4 * 4 + 2) * HID4 + cg]);
        float4 w3 = __ldg(&W4[(k4 * 4 + 3) * HID4 + cg]);
        fma4(a0, x0.x, w0); fma4(a0, x0.y, w1); fma4(a0, x0.z, w2); fma4(a0, x0.w, w3);
        fma4(a1, x1.x, w0); fma4(a1, x1.y, w1); fma4(a1, x1.z, w2); fma4(a1, x1.w, w3);
        fma4(a2, x2.x, w0); fma4(a2, x2.y, w1); fma4(a2, x2.z, w2); fma4(a2, x2.w, w3);
        fma4(a3, x3.x, w0); fma4(a3, x3.y, w1); fma4(a3, x3.z, w2); fma4(a3, x3.w, w3);
    }
    float4* O = (float4*)g_bufB;
    if (v0) O[r0 * HID4 + cg] = a0;
    if (v1) O[r1 * HID4 + cg] = a1;
    if (v2) O[r2 * HID4 + cg] = a2;
    if (v3) O[r3 * HID4 + cg] = a3;
}

// ---------------- layer-2 gather + self + bias + relu, 4x unroll ------------
__global__ void __launch_bounds__(256) k_gather2(const float* __restrict__ b2) {
    int w = (blockIdx.x * 256 + threadIdx.x) >> 5;
    int lane = threadIdx.x & 31;
    if (w >= NN) return;
    float di = g_dis[w];
    int e   = g_rowptr[w];
    int end = g_rowptr[w + 1];
    const float4* T = (const float4*)g_bufB;
    float sc = di * di;
    float4 self = T[w * HID4 + lane];
    float4 acc;
    acc.x = self.x * sc; acc.y = self.y * sc;
    acc.z = self.z * sc; acc.w = self.w * sc;
    int e4 = e + ((end - e) & ~3);
    for (; e < e4; e += 4) {
        int s0 = __ldg(&g_col[e]);
        int s1 = __ldg(&g_col[e + 1]);
        int s2 = __ldg(&g_col[e + 2]);
        int s3 = __ldg(&g_col[e + 3]);
        float n0 = __ldg(&g_dis[s0]) * di;
        float n1 = __ldg(&g_dis[s1]) * di;
        float n2 = __ldg(&g_dis[s2]) * di;
        float n3 = __ldg(&g_dis[s3]) * di;
        float4 u0 = __ldg(&T[s0 * HID4 + lane]);
        float4 u1 = __ldg(&T[s1 * HID4 + lane]);
        float4 u2 = __ldg(&T[s2 * HID4 + lane]);
        float4 u3 = __ldg(&T[s3 * HID4 + lane]);
        fma4(acc, n0, u0);
        fma4(acc, n1, u1);
        fma4(acc, n2, u2);
        fma4(acc, n3, u3);
    }
    for (; e < end; e++) {
        int s = __ldg(&g_col[e]);
        float nrm = __ldg(&g_dis[s]) * di;
        float4 v = __ldg(&T[s * HID4 + lane]);
        fma4(acc, nrm, v);
    }
    float4 b = ((const float4*)b2)[lane];
    acc.x = fmaxf(acc.x + b.x, 0.f); acc.y = fmaxf(acc.y + b.y, 0.f);
    acc.z = fmaxf(acc.z + b.z, 0.f); acc.w = fmaxf(acc.w + b.w, 0.f);
    ((float4*)g_bufA)[w * HID4 + lane] = acc;
}

// ---------------- mean pool over rows of bufA -> g_gsum (sum) ---------------
__global__ void __launch_bounds__(256) k_mean() {
    __shared__ float sred[256];
    int tid = threadIdx.x;
    int c = tid & 127, half = tid >> 7;
    float acc = 0.f;
    for (int i = blockIdx.x * 2 + half; i < NN; i += gridDim.x * 2)
        acc += g_bufA[i * HID + c];
    sred[tid] = acc;
    __syncthreads();
    if (tid < 128) atomicAdd(&g_gsum[c], sred[tid] + sred[tid + 128]);
}

// ---------------- head: mu, logvar (to out), z, d -> g_dvec -----------------
__global__ void __launch_bounds__(128) k_head(const float* __restrict__ eps,
                                              const float* __restrict__ Wmu, const float* __restrict__ bmu,
                                              const float* __restrict__ Wlv, const float* __restrict__ blv,
                                              const float* __restrict__ Wd1, const float* __restrict__ bd1,
                                              float* __restrict__ out) {
    __shared__ float gs[HID], zs[LAT];
    int tid = threadIdx.x;
    gs[tid] = g_gsum[tid] * (1.0f / (float)NN);
    __syncthreads();
    if (tid < LAT) {
        float mu = bmu[tid], lv = blv[tid];
#pragma unroll 4
        for (int k = 0; k < HID; k++) {
            float gk = gs[k];
            mu = fmaf(gk, Wmu[k * LAT + tid], mu);
            lv = fmaf(gk, Wlv[k * LAT + tid], lv);
        }
        out[(size_t)NN * CIN + tid] = mu;
        out[(size_t)NN * CIN + LAT + tid] = lv;
        zs[tid] = fmaf(eps[tid], expf(0.5f * lv), mu);
    }
    __syncthreads();
    float dv = bd1[tid];
#pragma unroll 4
    for (int k = 0; k < LAT; k++) dv = fmaf(zs[k], Wd1[k * HID + tid], dv);
    g_dvec[tid] = fmaxf(dv, 0.f);
}

// ---------------- decoder GEMV: out = d @ Wd2 + bd2 (819 MB stream) ---------
__global__ void __launch_bounds__(256) k_dec(const float* __restrict__ Wd2,
                                             const float* __restrict__ bd2,
                                             float* __restrict__ out) {
    __shared__ float ds[HID];
    int tid = threadIdx.x;
    if (tid < HID) ds[tid] = g_dvec[tid];
    __syncthreads();
    int j = blockIdx.x * 256 + tid;              // float4 column index
    const int NC4 = NN * CIN / 4;                // 400000
    if (j >= NC4) return;
    const float4* W = (const float4*)Wd2;
    float4 acc = ((const float4*)bd2)[j];
#pragma unroll 8
    for (int k = 0; k < HID; k++) {
        float dk = ds[k];
        fma4(acc, dk, W[(size_t)k * NC4 + j]);
    }
    ((float4*)out)[j] = acc;
}

// ---------------- launch ----------------------------------------------------
extern "C" void kernel_launch(void* const* d_in, const int* in_sizes, int n_in,
                              void* d_out, int out_size) {
    const float* x   = (const float*)d_in[0];
    const int*   ei  = (const int*)  d_in[1];
    const float* eps = (const float*)d_in[2];
    const float* W1  = (const float*)d_in[3];
    const float* b1  = (const float*)d_in[4];
    const float* W2  = (const float*)d_in[5];
    const float* b2  = (const float*)d_in[6];
    const float* Wmu = (const float*)d_in[7];
    const float* bmu = (const float*)d_in[8];
    const float* Wlv = (const float*)d_in[9];
    const float* blv = (const float*)d_in[10];
    const float* Wd1 = (const float*)d_in[11];
    const float* bd1 = (const float*)d_in[12];
    const float* Wd2 = (const float*)d_in[13];
    const float* bd2 = (const float*)d_in[14];
    float* out = (float*)d_out;

    (void)in_sizes; (void)n_in; (void)out_size;

    const int EQ = EE / 4;                                  // 400000 quads
    k_init   <<<(NN + 255) / 256, 256>>>();
    k_deg    <<<(EQ + 255) / 256, 256>>>(ei + EE);
    k_scan   <<<1, 1024>>>();
    k_fill   <<<(EQ + 255) / 256, 256>>>(ei);
    k_gather1<<<NN * 32 / 256, 256>>>(x);                   // warp/node
    k_layer1 <<<NN / 8, 256>>>(W1, b1);
    k_gemm2  <<<(NN + 31) / 32, 256>>>(W2);
    k_gather2<<<NN * 32 / 256, 256>>>(b2);                  // warp/node
    k_mean   <<<256, 256>>>();
    k_head   <<<1, 128>>>(eps, Wmu, bmu, Wlv, blv, Wd1, bd1, out);
    k_dec    <<<(NN * CIN / 4 + 255) / 256, 256>>>(Wd2, bd2, out);
}

// round 8
// speedup vs baseline: 1.1404x; 1.0221x over previous
#include <cuda_runtime.h>
#include <cuda_bf16.h>
#include <math.h>
#include <stdint.h>

#define NN   50000
#define EE   1600000
#define CIN  32
#define HID  128
#define LAT  64
#define HID4 (HID/4)
#define CIN4 (CIN/4)

// ---------------- scratch (device globals; no allocations allowed) ----------
__device__ int   g_ideg[NN];                 // in-degree (edges only)
__device__ int   g_cnt[NN];                  // fill cursors (init = rowptr)
__device__ int   g_rowptr[NN + 1];           // CSR row pointers
__device__ __align__(16) int2  g_coln[EE];   // per-edge {src, bits(nrm)}
__device__ __align__(16) float g_dis[NN];
__device__ __align__(16) __nv_bfloat16 g_xh[NN * CIN];   // bf16 copy of x
__device__ __align__(16) float g_aggx[NN * CIN];         // layer-1 GCN input
__device__ __align__(16) float g_bufA[NN * HID];         // h1
__device__ __align__(16) __nv_bfloat16 g_tB[NN * HID];   // t2 = h1@W2, bf16
__device__ __align__(16) float g_gsum[HID];
__device__ __align__(16) float g_dvec[HID];

__device__ __forceinline__ void fma4(float4& acc, float s, const float4& v) {
    acc.x = fmaf(s, v.x, acc.x);
    acc.y = fmaf(s, v.y, acc.y);
    acc.z = fmaf(s, v.z, acc.z);
    acc.w = fmaf(s, v.w, acc.w);
}

__device__ __forceinline__ uint32_t bf2_bits(__nv_bfloat162 v) {
    return *reinterpret_cast<uint32_t*>(&v);
}

__device__ __forceinline__ void fma_bf(float4& acc, float n, uint2 u) {
    __nv_bfloat162 lo = *reinterpret_cast<__nv_bfloat162*>(&u.x);
    __nv_bfloat162 hi = *reinterpret_cast<__nv_bfloat162*>(&u.y);
    float2 f0 = __bfloat1622float2(lo);
    float2 f1 = __bfloat1622float2(hi);
    acc.x = fmaf(n, f0.x, acc.x); acc.y = fmaf(n, f0.y, acc.y);
    acc.z = fmaf(n, f1.x, acc.z); acc.w = fmaf(n, f1.y, acc.w);
}

__device__ __forceinline__ void red_add_f4(float4* p, float4 v) {
    asm volatile("red.global.add.v4.f32 [%0], {%1,%2,%3,%4};"
                 :: "l"(p), "f"(v.x), "f"(v.y), "f"(v.z), "f"(v.w)
                 : "memory");
}

// ---------------- init: zero ideg/gsum + convert x -> bf16 ------------------
__global__ void k_init(const float* __restrict__ x) {
    int i = blockIdx.x * 256 + threadIdx.x;
    if (i < NN)  g_ideg[i] = 0;
    if (i < HID) g_gsum[i] = 0.0f;
    if (i < NN * CIN / 2) {
        float2 v = ((const float2*)x)[i];
        ((__nv_bfloat162*)g_xh)[i] = __float22bfloat162_rn(v);
    }
}

// ---------------- integer degree over dst: 4 edges / thread ----------------
__global__ void k_deg(const int* __restrict__ dst) {
    int e0 = (blockIdx.x * 256 + threadIdx.x) * 4;
    if (e0 >= EE) return;                      // EE % 4 == 0
    int4 d4 = *(const int4*)(dst + e0);
    atomicAdd(&g_ideg[d4.x], 1);
    atomicAdd(&g_ideg[d4.y], 1);
    atomicAdd(&g_ideg[d4.z], 1);
    atomicAdd(&g_ideg[d4.w], 1);
}

// ---------------- single-block scan -> rowptr, cnt(=rowptr), dis ------------
__global__ void __launch_bounds__(1024) k_scan() {
    const int CH = 49;                         // ceil(50000/1024)
    int tid = threadIdx.x;
    int base = tid * CH;
    int local = 0;
#pragma unroll
    for (int j = 0; j < CH; j++) {
        int i = base + j;
        if (i < NN) local += g_ideg[i];
    }
    __shared__ int wsum[32];
    int lane = tid & 31, wid = tid >> 5;
    int inc = local;
#pragma unroll
    for (int off = 1; off < 32; off <<= 1) {
        int t = __shfl_up_sync(0xffffffffu, inc, off);
        if (lane >= off) inc += t;
    }
    if (lane == 31) wsum[wid] = inc;
    __syncthreads();
    if (wid == 0) {
        int v = wsum[lane];
#pragma unroll
        for (int off = 1; off < 32; off <<= 1) {
            int t = __shfl_up_sync(0xffffffffu, v, off);
            if (lane >= off) v += t;
        }
        wsum[lane] = v;
    }
    __syncthreads();
    int run = inc - local + (wid > 0 ? wsum[wid - 1] : 0);   // exclusive prefix
#pragma unroll
    for (int j = 0; j < CH; j++) {
        int i = base + j;
        if (i < NN) {
            int d = g_ideg[i];
            g_rowptr[i] = run;
            g_cnt[i]    = run;                               // fill cursor base
            g_dis[i] = rsqrtf((float)(d + 1));               // +1 self loop
            run += d;
        }
    }
    if (tid == 1023) g_rowptr[NN] = run;
}

// ---------------- CSR fill: 4 edges/thread, store {src, nrm} ----------------
__global__ void k_fill(const int* __restrict__ ei) {
    int e0 = (blockIdx.x * 256 + threadIdx.x) * 4;
    if (e0 >= EE) return;
    int4 s4 = *(const int4*)(ei + e0);
    int4 d4 = *(const int4*)(ei + EE + e0);
    float a0 = __ldg(&g_dis[s4.x]) * __ldg(&g_dis[d4.x]);
    float a1 = __ldg(&g_dis[s4.y]) * __ldg(&g_dis[d4.y]);
    float a2 = __ldg(&g_dis[s4.z]) * __ldg(&g_dis[d4.z]);
    float a3 = __ldg(&g_dis[s4.w]) * __ldg(&g_dis[d4.w]);
    int p0 = atomicAdd(&g_cnt[d4.x], 1);       // global slot directly
    int p1 = atomicAdd(&g_cnt[d4.y], 1);
    int p2 = atomicAdd(&g_cnt[d4.z], 1);
    int p3 = atomicAdd(&g_cnt[d4.w], 1);
    g_coln[p0] = make_int2(s4.x, __float_as_int(a0));
    g_coln[p1] = make_int2(s4.y, __float_as_int(a1));
    g_coln[p2] = make_int2(s4.z, __float_as_int(a2));
    g_coln[p3] = make_int2(s4.w, __float_as_int(a3));
}

// ---------------- layer-1 gather (32 cols, bf16 payload), warp/node ---------
__global__ void __launch_bounds__(256) k_gather1() {
    int w = (blockIdx.x * 256 + threadIdx.x) >> 5;
    int lane = threadIdx.x & 31;
    if (w >= NN) return;
    float di = g_dis[w];
    int e   = g_rowptr[w];
    int end = g_rowptr[w + 1];
    float acc = __bfloat162float(g_xh[w * CIN + lane]) * di * di;
    int e4 = e + ((end - e) & ~3);
    for (; e < e4; e += 4) {
        int2 c0 = __ldg(&g_coln[e]);
        int2 c1 = __ldg(&g_coln[e + 1]);
        int2 c2 = __ldg(&g_coln[e + 2]);
        int2 c3 = __ldg(&g_coln[e + 3]);
        float v0 = __bfloat162float(g_xh[c0.x * CIN + lane]);
        float v1 = __bfloat162float(g_xh[c1.x * CIN + lane]);
        float v2 = __bfloat162float(g_xh[c2.x * CIN + lane]);
        float v3 = __bfloat162float(g_xh[c3.x * CIN + lane]);
        acc = fmaf(v0, __int_as_float(c0.y), acc);
        acc = fmaf(v1, __int_as_float(c1.y), acc);
        acc = fmaf(v2, __int_as_float(c2.y), acc);
        acc = fmaf(v3, __int_as_float(c3.y), acc);
    }
    for (; e < end; e++) {
        int2 c = __ldg(&g_coln[e]);
        acc = fmaf(__bfloat162float(g_xh[c.x * CIN + lane]),
                   __int_as_float(c.y), acc);
    }
    g_aggx[w * CIN + lane] = acc;
}

// ---------------- layer 1: h1 = relu(aggx @ W1 + b1) -> bufA ----------------
__global__ void __launch_bounds__(256) k_layer1(const float* __restrict__ W1,
                                                const float* __restrict__ b1) {
    __shared__ float sW[CIN * HID];   // 16 KB
    __shared__ float sv[8 * CIN];
    int tid = threadIdx.x;
    int row0 = blockIdx.x * 8;
    for (int i = tid; i < CIN * HID; i += 256) sW[i] = W1[i];
    sv[tid] = g_aggx[row0 * CIN + tid];
    __syncthreads();
    int r = tid >> 5, cg = tid & 31;
    float4 acc = ((const float4*)b1)[cg];
    const float4* sW4 = (const float4*)sW;
#pragma unroll
    for (int k = 0; k < CIN; k++) {
        float a = sv[r * CIN + k];
        fma4(acc, a, sW4[k * HID4 + cg]);
    }
    acc.x = fmaxf(acc.x, 0.f); acc.y = fmaxf(acc.y, 0.f);
    acc.z = fmaxf(acc.z, 0.f); acc.w = fmaxf(acc.w, 0.f);
    ((float4*)g_bufA)[(row0 + r) * HID4 + cg] = acc;
}

// ---------------- GEMM2: tB(bf16) = bufA @ W2 -------------------------------
__global__ void __launch_bounds__(256) k_gemm2(const float* __restrict__ W2) {
    int tid = threadIdx.x;
    int cg = tid & 31, rl = tid >> 5;
    int rbase = blockIdx.x * 32 + rl;
    int r0 = rbase, r1 = rbase + 8, r2 = rbase + 16, r3 = rbase + 24;
    bool v0 = r0 < NN, v1 = r1 < NN, v2 = r2 < NN, v3 = r3 < NN;
    const float4* W4 = (const float4*)W2;
    const float4* A4 = (const float4*)g_bufA;
    float4 zf = make_float4(0.f, 0.f, 0.f, 0.f);
    float4 a0 = zf, a1 = zf, a2 = zf, a3 = zf;
#pragma unroll 4
    for (int k4 = 0; k4 < HID4; k4++) {
        float4 x0 = v0 ? __ldg(&A4[r0 * HID4 + k4]) : zf;
        float4 x1 = v1 ? __ldg(&A4[r1 * HID4 + k4]) : zf;
        float4 x2 = v2 ? __ldg(&A4[r2 * HID4 + k4]) : zf;
        float4 x3 = v3 ? __ldg(&A4[r3 * HID4 + k4]) : zf;
        float4 w0 = __ldg(&W4[(k4 * 4 + 0) * HID4 + cg]);
        float4 w1 = __ldg(&W4[(k4 * 4 + 1) * HID4 + cg]);
        float4 w2 = __ldg(&W4[(k4 * 4 + 2) * HID4 + cg]);
        float4 w3 = __ldg(&W4[(k4 * 4 + 3) * HID4 + cg]);
        fma4(a0, x0.x, w0); fma4(a0, x0.y, w1); fma4(a0, x0.z, w2); fma4(a0, x0.w, w3);
        fma4(a1, x1.x, w0); fma4(a1, x1.y, w1); fma4(a1, x1.z, w2); fma4(a1, x1.w, w3);
        fma4(a2, x2.x, w0); fma4(a2, x2.y, w1); fma4(a2, x2.z, w2); fma4(a2, x2.w, w3);
        fma4(a3, x3.x, w0); fma4(a3, x3.y, w1); fma4(a3, x3.z, w2); fma4(a3, x3.w, w3);
    }
    uint2* O = (uint2*)g_tB;                   // 4 bf16 per uint2
    uint2 o;
    if (v0) {
        o.x = bf2_bits(__float22bfloat162_rn(make_float2(a0.x, a0.y)));
        o.y = bf2_bits(__float22bfloat162_rn(make_float2(a0.z, a0.w)));
        O[r0 * 32 + cg] = o;
    }
    if (v1) {
        o.x = bf2_bits(__float22bfloat162_rn(make_float2(a1.x, a1.y)));
        o.y = bf2_bits(__float22bfloat162_rn(make_float2(a1.z, a1.w)));
        O[r1 * 32 + cg] = o;
    }
    if (v2) {
        o.x = bf2_bits(__float22bfloat162_rn(make_float2(a2.x, a2.y)));
        o.y = bf2_bits(__float22bfloat162_rn(make_float2(a2.z, a2.w)));
        O[r2 * 32 + cg] = o;
    }
    if (v3) {
        o.x = bf2_bits(__float22bfloat162_rn(make_float2(a3.x, a3.y)));
        o.y = bf2_bits(__float22bfloat162_rn(make_float2(a3.z, a3.w)));
        O[r3 * 32 + cg] = o;
    }
}

// ---------------- layer-2 gather + bias + relu + fused mean -> gsum ---------
// warp/node (8 nodes/block, exact fit: NN/8 blocks); no h2 write at all.
__global__ void __launch_bounds__(256) k_gather2(const float* __restrict__ b2) {
    __shared__ float sacc[2 * HID];            // [2][128] col partials
    int tid = threadIdx.x;
    int w = blockIdx.x * 8 + (tid >> 5);
    int lane = tid & 31;
    float di = g_dis[w];
    int e   = g_rowptr[w];
    int end = g_rowptr[w + 1];
    const uint2* T2 = (const uint2*)g_tB;
    float sc = di * di;
    float4 acc = make_float4(0.f, 0.f, 0.f, 0.f);
    fma_bf(acc, sc, T2[w * 32 + lane]);        // self loop
    int e4 = e + ((end - e) & ~3);
    for (; e < e4; e += 4) {
        int2 c0 = __ldg(&g_coln[e]);
        int2 c1 = __ldg(&g_coln[e + 1]);
        int2 c2 = __ldg(&g_coln[e + 2]);
        int2 c3 = __ldg(&g_coln[e + 3]);
        uint2 u0 = __ldg(&T2[c0.x * 32 + lane]);
        uint2 u1 = __ldg(&T2[c1.x * 32 + lane]);
        uint2 u2 = __ldg(&T2[c2.x * 32 + lane]);
        uint2 u3 = __ldg(&T2[c3.x * 32 + lane]);
        fma_bf(acc, __int_as_float(c0.y), u0);
        fma_bf(acc, __int_as_float(c1.y), u1);
        fma_bf(acc, __int_as_float(c2.y), u2);
        fma_bf(acc, __int_as_float(c3.y), u3);
    }
    for (; e < end; e++) {
        int2 c = __ldg(&g_coln[e]);
        fma_bf(acc, __int_as_float(c.y), __ldg(&T2[c.x * 32 + lane]));
    }
    float4 b = ((const float4*)b2)[lane];
    acc.x = fmaxf(acc.x + b.x, 0.f); acc.y = fmaxf(acc.y + b.y, 0.f);
    acc.z = fmaxf(acc.z + b.z, 0.f); acc.w = fmaxf(acc.w + b.w, 0.f);
    // block reduction: 8 warps -> 2 -> 1, then one red.global per float4
    int half = tid >> 7;                       // 0: warps 0-3, 1: warps 4-7
    int wi   = (tid >> 5) & 3;                 // warp within half
    float4* s4 = (float4*)sacc;                // [2][32] float4
    if (wi == 0) s4[half * 32 + lane] = acc;
    __syncthreads();
    if (wi == 1) fma4(s4[half * 32 + lane], 1.f, acc);
    __syncthreads();
    if (wi == 2) fma4(s4[half * 32 + lane], 1.f, acc);
    __syncthreads();
    if (wi == 3) fma4(s4[half * 32 + lane], 1.f, acc);
    __syncthreads();
    if (tid < 32) {
        float4 v0 = s4[tid];
        float4 v1 = s4[32 + tid];
        v0.x += v1.x; v0.y += v1.y; v0.z += v1.z; v0.w += v1.w;
        red_add_f4(&((float4*)g_gsum)[tid], v0);
    }
}

// ---------------- head: mu, logvar (to out), z, d -> g_dvec -----------------
__global__ void __launch_bounds__(128) k_head(const float* __restrict__ eps,
                                              const float* __restrict__ Wmu, const float* __restrict__ bmu,
                                              const float* __restrict__ Wlv, const float* __restrict__ blv,
                                              const float* __restrict__ Wd1, const float* __restrict__ bd1,
                                              float* __restrict__ out) {
    __shared__ float gs[HID], zs[LAT];
    int tid = threadIdx.x;
    gs[tid] = g_gsum[tid] * (1.0f / (float)NN);
    __syncthreads();
    if (tid < LAT) {
        float mu = bmu[tid], lv = blv[tid];
#pragma unroll 4
        for (int k = 0; k < HID; k++) {
            float gk = gs[k];
            mu = fmaf(gk, Wmu[k * LAT + tid], mu);
            lv = fmaf(gk, Wlv[k * LAT + tid], lv);
        }
        out[(size_t)NN * CIN + tid] = mu;
        out[(size_t)NN * CIN + LAT + tid] = lv;
        zs[tid] = fmaf(eps[tid], expf(0.5f * lv), mu);
    }
    __syncthreads();
    float dv = bd1[tid];
#pragma unroll 4
    for (int k = 0; k < LAT; k++) dv = fmaf(zs[k], Wd1[k * HID + tid], dv);
    g_dvec[tid] = fmaxf(dv, 0.f);
}

// ---------------- decoder GEMV: out = d @ Wd2 + bd2 (819 MB stream) ---------
__global__ void __launch_bounds__(256) k_dec(const float* __restrict__ Wd2,
                                             const float* __restrict__ bd2,
                                             float* __restrict__ out) {
    __shared__ float ds[HID];
    int tid = threadIdx.x;
    if (tid < HID) ds[tid] = g_dvec[tid];
    __syncthreads();
    int j = blockIdx.x * 256 + tid;              // float4 column index
    const int NC4 = NN * CIN / 4;                // 400000
    if (j >= NC4) return;
    const float4* W = (const float4*)Wd2;
    float4 acc = ((const float4*)bd2)[j];
#pragma unroll 8
    for (int k = 0; k < HID; k++) {
        float dk = ds[k];
        fma4(acc, dk, W[(size_t)k * NC4 + j]);
    }
    ((float4*)out)[j] = acc;
}

// ---------------- launch ----------------------------------------------------
extern "C" void kernel_launch(void* const* d_in, const int* in_sizes, int n_in,
                              void* d_out, int out_size) {
    const float* x   = (const float*)d_in[0];
    const int*   ei  = (const int*)  d_in[1];
    const float* eps = (const float*)d_in[2];
    const float* W1  = (const float*)d_in[3];
    const float* b1  = (const float*)d_in[4];
    const float* W2  = (const float*)d_in[5];
    const float* b2  = (const float*)d_in[6];
    const float* Wmu = (const float*)d_in[7];
    const float* bmu = (const float*)d_in[8];
    const float* Wlv = (const float*)d_in[9];
    const float* blv = (const float*)d_in[10];
    const float* Wd1 = (const float*)d_in[11];
    const float* bd1 = (const float*)d_in[12];
    const float* Wd2 = (const float*)d_in[13];
    const float* bd2 = (const float*)d_in[14];
    float* out = (float*)d_out;

    (void)in_sizes; (void)n_in; (void)out_size;

    const int EQ = EE / 4;                                  // 400000 quads
    k_init   <<<(NN * CIN / 2 + 255) / 256, 256>>>(x);      // also converts x
    k_deg    <<<(EQ + 255) / 256, 256>>>(ei + EE);
    k_scan   <<<1, 1024>>>();
    k_fill   <<<(EQ + 255) / 256, 256>>>(ei);
    k_gather1<<<NN * 32 / 256, 256>>>();                    // warp/node
    k_layer1 <<<NN / 8, 256>>>(W1, b1);
    k_gemm2  <<<(NN + 31) / 32, 256>>>(W2);
    k_gather2<<<NN / 8, 256>>>(b2);                         // warp/node + mean
    k_head   <<<1, 128>>>(eps, Wmu, bmu, Wlv, blv, Wd1, bd1, out);
    k_dec    <<<(NN * CIN / 4 + 255) / 256, 256>>>(Wd2, bd2, out);
}